// round 8
// baseline (speedup 1.0000x reference)
#include <cuda_runtime.h>
#include <cuda_fp16.h>
#include <math.h>
#include <stdint.h>

// Problem constants
#define BATCH_M   16384   // B*S
#define DIM_D     768
#define DIM_N     2304    // 3*D
#define NUM_T     10
#define RANK_R    16
#define SEG       (RANK_R * DIM_D)

// GEMM tiling (R5 config — proven fastest): CTA 128x128, 8 warps, BK=32
#define BM 128
#define BN 128
#define BK 32
#define KSTAGES (DIM_D / BK)       // 24

#define ROWB     80
#define ARRB     10240             // 128 rows * 80B
#define STAGEB   20480
#define NSTAGE   4
#define SMEM_TOTAL (NSTAGE * STAGEB)

// Fused prep kernel grid split
#define NCONV_BLOCKS 12288         // convert_x: 12288 blocks * 256 thr * 4 elems
#define WEFF_DTILES  3             // 768 / 256
#define WEFF_EROWS   8
#define WEFF_ETILES  (DIM_N / WEFF_EROWS)   // 288

// Device scratch (no cudaMalloc allowed)
__device__ float g_wq[NUM_T];
__device__ float g_wv[NUM_T];
__device__ __align__(16) unsigned short g_Xh[(size_t)BATCH_M * DIM_D];
__device__ __align__(16) unsigned short g_Wh[(size_t)DIM_N * DIM_D];

// ---------------------------------------------------------------------------
// Helpers
// ---------------------------------------------------------------------------
__device__ __forceinline__ uint32_t smem_u32(const void* p) {
    uint32_t a;
    asm("{ .reg .u64 t; cvta.to.shared.u64 t, %1; cvt.u32.u64 %0, t; }" : "=r"(a) : "l"(p));
    return a;
}
#define CP16(dst, src) \
    asm volatile("cp.async.cg.shared.global [%0], [%1], 16;" :: "r"(dst), "l"(src))
#define CP_COMMIT() asm volatile("cp.async.commit_group;" ::: "memory")
#define CP_WAIT2()  asm volatile("cp.async.wait_group 2;"  ::: "memory")

__device__ __forceinline__ void ldsm_x4(uint32_t* r, uint32_t addr) {
    asm volatile("ldmatrix.sync.aligned.m8n8.x4.shared.b16 {%0,%1,%2,%3}, [%4];"
        : "=r"(r[0]), "=r"(r[1]), "=r"(r[2]), "=r"(r[3]) : "r"(addr));
}
__device__ __forceinline__ void mma_fp16(float* c, const uint32_t* a,
                                         uint32_t b0, uint32_t b1) {
    asm volatile("mma.sync.aligned.m16n8k16.row.col.f32.f16.f16.f32 "
        "{%0,%1,%2,%3},{%4,%5,%6,%7},{%8,%9},{%0,%1,%2,%3};"
        : "+f"(c[0]), "+f"(c[1]), "+f"(c[2]), "+f"(c[3])
        : "r"(a[0]), "r"(a[1]), "r"(a[2]), "r"(a[3]), "r"(b0), "r"(b1));
}

// ---------------------------------------------------------------------------
// Kernel 1: fused per-task Frobenius sums + softmax gate weights.
// One block, 1024 threads: warp w reduces segment(s) w, w+32; then thread 0
// computes the folded weights.
// ---------------------------------------------------------------------------
__global__ __launch_bounds__(1024)
void k_prep0(const float* __restrict__ Aq, const float* __restrict__ Bq,
             const float* __restrict__ Av, const float* __restrict__ Bv,
             const float* __restrict__ logits, const float* __restrict__ alpha) {
    __shared__ float ssq[40];
    const int w   = threadIdx.x >> 5;
    const int lane = threadIdx.x & 31;

    for (int seg = w; seg < 40; seg += 32) {
        const float* base;
        switch (seg / NUM_T) {
            case 0:  base = Aq; break;
            case 1:  base = Bq; break;
            case 2:  base = Av; break;
            default: base = Bv; break;
        }
        const float4* p = (const float4*)(base + (seg % NUM_T) * SEG);
        float s = 0.f;
        for (int i = lane; i < SEG / 4; i += 32) {
            float4 v = __ldg(p + i);
            s += v.x * v.x + v.y * v.y + v.z * v.z + v.w * v.w;
        }
        #pragma unroll
        for (int o = 16; o > 0; o >>= 1)
            s += __shfl_xor_sync(0xFFFFFFFF, s, o);
        if (lane == 0) ssq[seg] = s;
    }
    __syncthreads();
    if (threadIdx.x == 0) {
        float mx = -1e30f;
        for (int t = 0; t < NUM_T; t++) mx = fmaxf(mx, logits[t]);
        float e[NUM_T], se = 0.f;
        for (int t = 0; t < NUM_T; t++) { e[t] = expf(logits[t] - mx); se += e[t]; }
        for (int t = 0; t < NUM_T; t++) {
            float coef = (e[t] / se) * alpha[t];
            g_wq[t] = coef / (sqrtf(ssq[t])      * sqrtf(ssq[10 + t]) + 1e-8f);
            g_wv[t] = coef / (sqrtf(ssq[20 + t]) * sqrtf(ssq[30 + t]) + 1e-8f);
        }
    }
}

// ---------------------------------------------------------------------------
// Kernel 2: fused prep — grid-partitioned.
//   blocks [0, NCONV_BLOCKS):       quantize X -> fp16 (HBM bound)
//   blocks [NCONV_BLOCKS, +864):    build W_eff -> fp16 (L2-latency bound)
// ---------------------------------------------------------------------------
__global__ __launch_bounds__(256)
void k_prep1(const float* __restrict__ x,
             const float* __restrict__ Aq, const float* __restrict__ Bq,
             const float* __restrict__ Av, const float* __restrict__ Bv,
             const float* __restrict__ qkvw) {
    if (blockIdx.x < NCONV_BLOCKS) {
        // ---- convert X ----
        size_t i = ((size_t)blockIdx.x * 256 + threadIdx.x) * 4;
        float4 v = __ldg((const float4*)(x + i));
        __half h0 = __float2half(v.x), h1 = __float2half(v.y),
               h2 = __float2half(v.z), h3 = __float2half(v.w);
        uint2 hh = make_uint2(
            (uint32_t)__half_as_ushort(h0) | ((uint32_t)__half_as_ushort(h1) << 16),
            (uint32_t)__half_as_ushort(h2) | ((uint32_t)__half_as_ushort(h3) << 16));
        *(uint2*)(g_Xh + i) = hh;
        return;
    }

    // ---- W_eff: 8 e-rows x 256 d-cols per block ----
    const int bid = blockIdx.x - NCONV_BLOCKS;
    const int d   = (bid % WEFF_DTILES) * 256 + threadIdx.x;
    const int e0  = (bid / WEFF_DTILES) * WEFF_EROWS;
    const int tx  = threadIdx.x;

    float acc[WEFF_EROWS];
    #pragma unroll
    for (int e = 0; e < WEFF_EROWS; e++) acc[e] = 0.f;

    bool is_q = (e0 < DIM_D);
    bool is_v = (e0 >= 2 * DIM_D);
    if (is_q || is_v) {
        __shared__ __align__(16) float sB[NUM_T * RANK_R * WEFF_EROWS];  // [i][e]
        const float* Am = is_q ? Aq : Av;
        const float* Bm = is_q ? Bq : Bv;
        int el0 = is_q ? e0 : (e0 - 2 * DIM_D);
        for (int idx = tx; idx < NUM_T * RANK_R * WEFF_EROWS; idx += 256) {
            int i = idx >> 3, e = idx & 7;
            int t = i >> 4,  r = i & 15;
            float w = is_q ? g_wq[t] : g_wv[t];
            sB[idx] = w * Bm[((size_t)t * DIM_D + el0 + e) * RANK_R + r];
        }
        __syncthreads();

        const float4* sB4 = (const float4*)sB;
        #pragma unroll 32
        for (int i = 0; i < NUM_T * RANK_R; i++) {
            float a = __ldg(Am + (size_t)i * DIM_D + d);
            float4 b0 = sB4[i * 2 + 0];
            float4 b1 = sB4[i * 2 + 1];
            acc[0] += a * b0.x;  acc[1] += a * b0.y;
            acc[2] += a * b0.z;  acc[3] += a * b0.w;
            acc[4] += a * b1.x;  acc[5] += a * b1.y;
            acc[6] += a * b1.z;  acc[7] += a * b1.w;
        }
    }
    #pragma unroll
    for (int e = 0; e < WEFF_EROWS; e++) {
        float val = qkvw[(size_t)(e0 + e) * DIM_D + d] + acc[e];
        g_Wh[(size_t)(e0 + e) * DIM_D + d] = __half_as_ushort(__float2half(val));
    }
}

// ---------------------------------------------------------------------------
// Kernel 3: HMMA GEMM  out = Xh @ Wh^T + bias   (R5 config, verbatim)
// ---------------------------------------------------------------------------
__global__ __launch_bounds__(256, 2)
void k_gemm_mma(const float* __restrict__ bias, float* __restrict__ out) {
    extern __shared__ __align__(128) char smem[];
    const uint32_t sb = smem_u32(smem);
    const int tid = threadIdx.x;
    const int lid = tid & 31;
    const int wid = tid >> 5;
    const int wm = wid & 3;          // 4 warps in M, 32 rows each
    const int wn = wid >> 2;         // 2 warps in N, 64 cols each
    const int m0 = blockIdx.y * BM;
    const int n0 = blockIdx.x * BN;

    float acc[2][8][4];
    #pragma unroll
    for (int i = 0; i < 2; i++)
        #pragma unroll
        for (int j = 0; j < 8; j++)
            #pragma unroll
            for (int q = 0; q < 4; q++) acc[i][j][q] = 0.f;

    const uint32_t a_off = (uint32_t)(lid & 15) * ROWB + (uint32_t)(lid >> 4) * 16;
    const int b_nloc = (lid < 16) ? (lid & 7) : 8 + (lid & 7);
    const uint32_t b_off = (uint32_t)b_nloc * ROWB + (uint32_t)((lid >> 3) & 1) * 16;

    auto load_stage = [&](int s) {
        uint32_t buf = sb + (uint32_t)(s % NSTAGE) * STAGEB;
        int k0 = s * BK;
        #pragma unroll
        for (int i = 0; i < 4; i++) {
            int v = tid + i * 256;
            int arr = v >> 9;            // 0: Xh, 1: Wh
            int idx = v & 511;
            int r = idx >> 2, c = idx & 3;
            uint32_t dst = buf + (uint32_t)arr * ARRB + (uint32_t)r * ROWB + (uint32_t)c * 16;
            const unsigned short* src = arr == 0
                ? g_Xh + (size_t)(m0 + r) * DIM_D + k0 + c * 8
                : g_Wh + (size_t)(n0 + r) * DIM_D + k0 + c * 8;
            CP16(dst, src);
        }
    };

    load_stage(0); CP_COMMIT();
    load_stage(1); CP_COMMIT();
    load_stage(2); CP_COMMIT();

    for (int s = 0; s < KSTAGES; s++) {
        CP_WAIT2();
        __syncthreads();
        if (s + 3 < KSTAGES) load_stage(s + 3);
        CP_COMMIT();

        uint32_t buf = sb + (uint32_t)(s % NSTAGE) * STAGEB;
        #pragma unroll
        for (int kk = 0; kk < 2; kk++) {
            uint32_t koff = (uint32_t)kk * 32;
            uint32_t ra[2][4];
            #pragma unroll
            for (int mt = 0; mt < 2; mt++)
                ldsm_x4(ra[mt], buf + (uint32_t)(wm * 32 + mt * 16) * ROWB + koff + a_off);
            #pragma unroll
            for (int half = 0; half < 2; half++) {
                uint32_t rb[2][4];
                #pragma unroll
                for (int g = 0; g < 2; g++)
                    ldsm_x4(rb[g], buf + ARRB +
                        (uint32_t)(wn * 64 + (half * 2 + g) * 16) * ROWB + koff + b_off);
                #pragma unroll
                for (int mt = 0; mt < 2; mt++)
                    #pragma unroll
                    for (int n4 = 0; n4 < 4; n4++) {
                        uint32_t b0 = rb[n4 >> 1][(n4 & 1) * 2];
                        uint32_t b1 = rb[n4 >> 1][(n4 & 1) * 2 + 1];
                        mma_fp16(acc[mt][half * 4 + n4], ra[mt], b0, b1);
                    }
            }
        }
    }

    const int r0 = m0 + wm * 32 + (lid >> 2);
    const int cb = n0 + wn * 64 + (lid & 3) * 2;
    #pragma unroll
    for (int nt = 0; nt < 8; nt++) {
        float2 bv = *(const float2*)(bias + cb + nt * 8);
        #pragma unroll
        for (int mt = 0; mt < 2; mt++) {
            int r = r0 + mt * 16;
            float2 v0 = make_float2(acc[mt][nt][0] + bv.x, acc[mt][nt][1] + bv.y);
            float2 v1 = make_float2(acc[mt][nt][2] + bv.x, acc[mt][nt][3] + bv.y);
            *(float2*)(out + (size_t)r * DIM_N + cb + nt * 8) = v0;
            *(float2*)(out + (size_t)(r + 8) * DIM_N + cb + nt * 8) = v1;
        }
    }
}

// ---------------------------------------------------------------------------
// Launch
// ---------------------------------------------------------------------------
extern "C" void kernel_launch(void* const* d_in, const int* in_sizes, int n_in,
                              void* d_out, int out_size) {
    const float* x      = (const float*)d_in[0];
    const float* Aq     = (const float*)d_in[1];
    const float* Bq     = (const float*)d_in[2];
    const float* Av     = (const float*)d_in[3];
    const float* Bv     = (const float*)d_in[4];
    const float* qkvw   = (const float*)d_in[5];
    const float* qkvb   = (const float*)d_in[6];
    const float* logits = (const float*)d_in[7];
    const float* alpha  = (const float*)d_in[8];
    float* out = (float*)d_out;

    cudaFuncSetAttribute(k_gemm_mma, cudaFuncAttributeMaxDynamicSharedMemorySize, SMEM_TOTAL);

    k_prep0   <<<1, 1024>>>(Aq, Bq, Av, Bv, logits, alpha);
    k_prep1   <<<NCONV_BLOCKS + WEFF_DTILES * WEFF_ETILES, 256>>>(x, Aq, Bq, Av, Bv, qkvw);
    k_gemm_mma<<<dim3(DIM_N / BN, BATCH_M / BM), 256, SMEM_TOTAL>>>(qkvb, out);
}

// round 9
// speedup vs baseline: 1.0813x; 1.0813x over previous
#include <cuda_runtime.h>
#include <cuda_fp16.h>
#include <math.h>
#include <stdint.h>

// Problem constants
#define BATCH_M   16384   // B*S
#define DIM_D     768
#define DIM_N     2304    // 3*D
#define NUM_T     10
#define RANK_R    16
#define SEG       (RANK_R * DIM_D)

// GEMM tiling (R5 config — proven fastest): CTA 128x128, 8 warps, BK=32
#define BM 128
#define BN 128
#define BK 32
#define KSTAGES (DIM_D / BK)       // 24

#define ROWB     80
#define ARRB     10240             // 128 rows * 80B
#define STAGEB   20480
#define NSTAGE   4
#define SMEM_TOTAL (NSTAGE * STAGEB)

// Fused prep kernel grid split
#define NCONV_BLOCKS 12288         // convert_x: 12288 blocks * 256 thr * 4 elems
#define WEFF_DTILES  3             // 768 / 256
#define WEFF_EROWS   8
#define WEFF_ETILES  (DIM_N / WEFF_EROWS)   // 288

// Device scratch (no cudaMalloc allowed)
__device__ float g_sumsq[40];
__device__ __align__(16) unsigned short g_Xh[(size_t)BATCH_M * DIM_D];
__device__ __align__(16) unsigned short g_Wh[(size_t)DIM_N * DIM_D];

// ---------------------------------------------------------------------------
// Helpers
// ---------------------------------------------------------------------------
__device__ __forceinline__ uint32_t smem_u32(const void* p) {
    uint32_t a;
    asm("{ .reg .u64 t; cvta.to.shared.u64 t, %1; cvt.u32.u64 %0, t; }" : "=r"(a) : "l"(p));
    return a;
}
#define CP16(dst, src) \
    asm volatile("cp.async.cg.shared.global [%0], [%1], 16;" :: "r"(dst), "l"(src))
#define CP_COMMIT() asm volatile("cp.async.commit_group;" ::: "memory")
#define CP_WAIT2()  asm volatile("cp.async.wait_group 2;"  ::: "memory")

__device__ __forceinline__ void ldsm_x4(uint32_t* r, uint32_t addr) {
    asm volatile("ldmatrix.sync.aligned.m8n8.x4.shared.b16 {%0,%1,%2,%3}, [%4];"
        : "=r"(r[0]), "=r"(r[1]), "=r"(r[2]), "=r"(r[3]) : "r"(addr));
}
__device__ __forceinline__ void mma_fp16(float* c, const uint32_t* a,
                                         uint32_t b0, uint32_t b1) {
    asm volatile("mma.sync.aligned.m16n8k16.row.col.f32.f16.f16.f32 "
        "{%0,%1,%2,%3},{%4,%5,%6,%7},{%8,%9},{%0,%1,%2,%3};"
        : "+f"(c[0]), "+f"(c[1]), "+f"(c[2]), "+f"(c[3])
        : "r"(a[0]), "r"(a[1]), "r"(a[2]), "r"(a[3]), "r"(b0), "r"(b1));
}

// ---------------------------------------------------------------------------
// Kernel 1: per-task Frobenius sum-of-squares. 40 blocks x 256 threads,
// float4 loads + warp-shuffle reduction.
// ---------------------------------------------------------------------------
__global__ __launch_bounds__(256)
void k_sumsq(const float* __restrict__ Aq, const float* __restrict__ Bq,
             const float* __restrict__ Av, const float* __restrict__ Bv) {
    int b = blockIdx.x;
    const float* base;
    switch (b / NUM_T) {
        case 0:  base = Aq; break;
        case 1:  base = Bq; break;
        case 2:  base = Av; break;
        default: base = Bv; break;
    }
    const float4* p = (const float4*)(base + (b % NUM_T) * SEG);
    float s = 0.f;
    for (int i = threadIdx.x; i < SEG / 4; i += 256) {
        float4 v = __ldg(p + i);
        s += v.x * v.x + v.y * v.y + v.z * v.z + v.w * v.w;
    }
    #pragma unroll
    for (int o = 16; o > 0; o >>= 1)
        s += __shfl_xor_sync(0xFFFFFFFF, s, o);
    __shared__ float red[8];
    if ((threadIdx.x & 31) == 0) red[threadIdx.x >> 5] = s;
    __syncthreads();
    if (threadIdx.x == 0) {
        float t = 0.f;
        #pragma unroll
        for (int i = 0; i < 8; i++) t += red[i];
        g_sumsq[b] = t;
    }
}

// ---------------------------------------------------------------------------
// Kernel 2: fused prep — grid-partitioned.
//   blocks [0, NCONV_BLOCKS):    quantize X -> fp16 (HBM bound)
//   blocks [NCONV_BLOCKS, +864): build W_eff -> fp16 (L2-latency bound),
//                                softmax weights computed inline per block.
// ---------------------------------------------------------------------------
__global__ __launch_bounds__(256)
void k_prep1(const float* __restrict__ x,
             const float* __restrict__ Aq, const float* __restrict__ Bq,
             const float* __restrict__ Av, const float* __restrict__ Bv,
             const float* __restrict__ qkvw,
             const float* __restrict__ logits, const float* __restrict__ alpha) {
    if (blockIdx.x < NCONV_BLOCKS) {
        // ---- convert X ----
        size_t i = ((size_t)blockIdx.x * 256 + threadIdx.x) * 4;
        float4 v = __ldg((const float4*)(x + i));
        __half h0 = __float2half(v.x), h1 = __float2half(v.y),
               h2 = __float2half(v.z), h3 = __float2half(v.w);
        uint2 hh = make_uint2(
            (uint32_t)__half_as_ushort(h0) | ((uint32_t)__half_as_ushort(h1) << 16),
            (uint32_t)__half_as_ushort(h2) | ((uint32_t)__half_as_ushort(h3) << 16));
        *(uint2*)(g_Xh + i) = hh;
        return;
    }

    // ---- W_eff: 8 e-rows x 256 d-cols per block ----
    const int bid = blockIdx.x - NCONV_BLOCKS;
    const int d   = (bid % WEFF_DTILES) * 256 + threadIdx.x;
    const int e0  = (bid / WEFF_DTILES) * WEFF_EROWS;
    const int tx  = threadIdx.x;

    float acc[WEFF_EROWS];
    #pragma unroll
    for (int e = 0; e < WEFF_EROWS; e++) acc[e] = 0.f;

    bool is_q = (e0 < DIM_D);
    bool is_v = (e0 >= 2 * DIM_D);
    if (is_q || is_v) {
        __shared__ float sw[NUM_T];
        __shared__ __align__(16) float sB[NUM_T * RANK_R * WEFF_EROWS];  // [i][e]

        // Inline softmax gate weights (first warp; tiny)
        if (tx == 0) {
            float mx = -1e30f;
            float lg[NUM_T];
            #pragma unroll
            for (int t = 0; t < NUM_T; t++) { lg[t] = __ldg(logits + t); mx = fmaxf(mx, lg[t]); }
            float e[NUM_T], se = 0.f;
            #pragma unroll
            for (int t = 0; t < NUM_T; t++) { e[t] = expf(lg[t] - mx); se += e[t]; }
            #pragma unroll
            for (int t = 0; t < NUM_T; t++) {
                float coef = (e[t] / se) * __ldg(alpha + t);
                float nq, nv;
                if (is_q) nq = sqrtf(g_sumsq[t])      * sqrtf(g_sumsq[10 + t]);
                else      nq = 0.f;
                if (is_v) nv = sqrtf(g_sumsq[20 + t]) * sqrtf(g_sumsq[30 + t]);
                else      nv = 0.f;
                sw[t] = is_q ? (coef / (nq + 1e-8f)) : (coef / (nv + 1e-8f));
            }
        }
        __syncthreads();

        const float* Am = is_q ? Aq : Av;
        const float* Bm = is_q ? Bq : Bv;
        int el0 = is_q ? e0 : (e0 - 2 * DIM_D);
        for (int idx = tx; idx < NUM_T * RANK_R * WEFF_EROWS; idx += 256) {
            int i = idx >> 3, e = idx & 7;
            int t = i >> 4,  r = i & 15;
            sB[idx] = sw[t] * Bm[((size_t)t * DIM_D + el0 + e) * RANK_R + r];
        }
        __syncthreads();

        const float4* sB4 = (const float4*)sB;
        #pragma unroll 32
        for (int i = 0; i < NUM_T * RANK_R; i++) {
            float a = __ldg(Am + (size_t)i * DIM_D + d);
            float4 b0 = sB4[i * 2 + 0];
            float4 b1 = sB4[i * 2 + 1];
            acc[0] += a * b0.x;  acc[1] += a * b0.y;
            acc[2] += a * b0.z;  acc[3] += a * b0.w;
            acc[4] += a * b1.x;  acc[5] += a * b1.y;
            acc[6] += a * b1.z;  acc[7] += a * b1.w;
        }
    }
    #pragma unroll
    for (int e = 0; e < WEFF_EROWS; e++) {
        float val = qkvw[(size_t)(e0 + e) * DIM_D + d] + acc[e];
        g_Wh[(size_t)(e0 + e) * DIM_D + d] = __half_as_ushort(__float2half(val));
    }
}

// ---------------------------------------------------------------------------
// Kernel 3: HMMA GEMM  out = Xh @ Wh^T + bias   (R5 config, verbatim)
// ---------------------------------------------------------------------------
__global__ __launch_bounds__(256, 2)
void k_gemm_mma(const float* __restrict__ bias, float* __restrict__ out) {
    extern __shared__ __align__(128) char smem[];
    const uint32_t sb = smem_u32(smem);
    const int tid = threadIdx.x;
    const int lid = tid & 31;
    const int wid = tid >> 5;
    const int wm = wid & 3;          // 4 warps in M, 32 rows each
    const int wn = wid >> 2;         // 2 warps in N, 64 cols each
    const int m0 = blockIdx.y * BM;
    const int n0 = blockIdx.x * BN;

    float acc[2][8][4];
    #pragma unroll
    for (int i = 0; i < 2; i++)
        #pragma unroll
        for (int j = 0; j < 8; j++)
            #pragma unroll
            for (int q = 0; q < 4; q++) acc[i][j][q] = 0.f;

    const uint32_t a_off = (uint32_t)(lid & 15) * ROWB + (uint32_t)(lid >> 4) * 16;
    const int b_nloc = (lid < 16) ? (lid & 7) : 8 + (lid & 7);
    const uint32_t b_off = (uint32_t)b_nloc * ROWB + (uint32_t)((lid >> 3) & 1) * 16;

    auto load_stage = [&](int s) {
        uint32_t buf = sb + (uint32_t)(s % NSTAGE) * STAGEB;
        int k0 = s * BK;
        #pragma unroll
        for (int i = 0; i < 4; i++) {
            int v = tid + i * 256;
            int arr = v >> 9;            // 0: Xh, 1: Wh
            int idx = v & 511;
            int r = idx >> 2, c = idx & 3;
            uint32_t dst = buf + (uint32_t)arr * ARRB + (uint32_t)r * ROWB + (uint32_t)c * 16;
            const unsigned short* src = arr == 0
                ? g_Xh + (size_t)(m0 + r) * DIM_D + k0 + c * 8
                : g_Wh + (size_t)(n0 + r) * DIM_D + k0 + c * 8;
            CP16(dst, src);
        }
    };

    load_stage(0); CP_COMMIT();
    load_stage(1); CP_COMMIT();
    load_stage(2); CP_COMMIT();

    for (int s = 0; s < KSTAGES; s++) {
        CP_WAIT2();
        __syncthreads();
        if (s + 3 < KSTAGES) load_stage(s + 3);
        CP_COMMIT();

        uint32_t buf = sb + (uint32_t)(s % NSTAGE) * STAGEB;
        #pragma unroll
        for (int kk = 0; kk < 2; kk++) {
            uint32_t koff = (uint32_t)kk * 32;
            uint32_t ra[2][4];
            #pragma unroll
            for (int mt = 0; mt < 2; mt++)
                ldsm_x4(ra[mt], buf + (uint32_t)(wm * 32 + mt * 16) * ROWB + koff + a_off);
            #pragma unroll
            for (int half = 0; half < 2; half++) {
                uint32_t rb[2][4];
                #pragma unroll
                for (int g = 0; g < 2; g++)
                    ldsm_x4(rb[g], buf + ARRB +
                        (uint32_t)(wn * 64 + (half * 2 + g) * 16) * ROWB + koff + b_off);
                #pragma unroll
                for (int mt = 0; mt < 2; mt++)
                    #pragma unroll
                    for (int n4 = 0; n4 < 4; n4++) {
                        uint32_t b0 = rb[n4 >> 1][(n4 & 1) * 2];
                        uint32_t b1 = rb[n4 >> 1][(n4 & 1) * 2 + 1];
                        mma_fp16(acc[mt][half * 4 + n4], ra[mt], b0, b1);
                    }
            }
        }
    }

    const int r0 = m0 + wm * 32 + (lid >> 2);
    const int cb = n0 + wn * 64 + (lid & 3) * 2;
    #pragma unroll
    for (int nt = 0; nt < 8; nt++) {
        float2 bv = *(const float2*)(bias + cb + nt * 8);
        #pragma unroll
        for (int mt = 0; mt < 2; mt++) {
            int r = r0 + mt * 16;
            float2 v0 = make_float2(acc[mt][nt][0] + bv.x, acc[mt][nt][1] + bv.y);
            float2 v1 = make_float2(acc[mt][nt][2] + bv.x, acc[mt][nt][3] + bv.y);
            *(float2*)(out + (size_t)r * DIM_N + cb + nt * 8) = v0;
            *(float2*)(out + (size_t)(r + 8) * DIM_N + cb + nt * 8) = v1;
        }
    }
}

// ---------------------------------------------------------------------------
// Launch
// ---------------------------------------------------------------------------
extern "C" void kernel_launch(void* const* d_in, const int* in_sizes, int n_in,
                              void* d_out, int out_size) {
    const float* x      = (const float*)d_in[0];
    const float* Aq     = (const float*)d_in[1];
    const float* Bq     = (const float*)d_in[2];
    const float* Av     = (const float*)d_in[3];
    const float* Bv     = (const float*)d_in[4];
    const float* qkvw   = (const float*)d_in[5];
    const float* qkvb   = (const float*)d_in[6];
    const float* logits = (const float*)d_in[7];
    const float* alpha  = (const float*)d_in[8];
    float* out = (float*)d_out;

    cudaFuncSetAttribute(k_gemm_mma, cudaFuncAttributeMaxDynamicSharedMemorySize, SMEM_TOTAL);

    k_sumsq   <<<40, 256>>>(Aq, Bq, Av, Bv);
    k_prep1   <<<NCONV_BLOCKS + WEFF_DTILES * WEFF_ETILES, 256>>>(
                  x, Aq, Bq, Av, Bv, qkvw, logits, alpha);
    k_gemm_mma<<<dim3(DIM_N / BN, BATCH_M / BM), 256, SMEM_TOTAL>>>(qkvb, out);
}

// round 10
// speedup vs baseline: 1.1241x; 1.0396x over previous
#include <cuda_runtime.h>
#include <cuda_fp16.h>
#include <math.h>
#include <stdint.h>

// Problem constants
#define BATCH_M   16384   // B*S
#define DIM_D     768
#define DIM_N     2304    // 3*D
#define NUM_T     10
#define RANK_R    16
#define SEG       (RANK_R * DIM_D)

// GEMM tiling (R5 config — proven fastest): CTA 128x128, 8 warps, BK=32
#define BM 128
#define BN 128
#define BK 32
#define KSTAGES (DIM_D / BK)       // 24

#define ROWB     80
#define ARRB     10240             // 128 rows * 80B
#define STAGEB   20480
#define NSTAGE   4
#define SMEM_TOTAL (NSTAGE * STAGEB)

// prep0 grid split: convert blocks then sumsq blocks
#define NCONV_BLOCKS 12288         // 12288 blocks * 256 thr * 4 elems = X
#define NSUMSQ_BLOCKS 40

// weff tiling
#define WEFF_DTILES  3             // 768 / 256
#define WEFF_EROWS   8
#define WEFF_ETILES  (DIM_N / WEFF_EROWS)   // 288

// Device scratch (no cudaMalloc allowed)
__device__ float g_sumsq[40];
__device__ __align__(16) unsigned short g_Xh[(size_t)BATCH_M * DIM_D];
__device__ __align__(16) unsigned short g_Wh[(size_t)DIM_N * DIM_D];

// ---------------------------------------------------------------------------
// Helpers
// ---------------------------------------------------------------------------
__device__ __forceinline__ uint32_t smem_u32(const void* p) {
    uint32_t a;
    asm("{ .reg .u64 t; cvta.to.shared.u64 t, %1; cvt.u32.u64 %0, t; }" : "=r"(a) : "l"(p));
    return a;
}
#define CP16(dst, src) \
    asm volatile("cp.async.cg.shared.global [%0], [%1], 16;" :: "r"(dst), "l"(src))
#define CP_COMMIT() asm volatile("cp.async.commit_group;" ::: "memory")
#define CP_WAIT2()  asm volatile("cp.async.wait_group 2;"  ::: "memory")

__device__ __forceinline__ void ldsm_x4(uint32_t* r, uint32_t addr) {
    asm volatile("ldmatrix.sync.aligned.m8n8.x4.shared.b16 {%0,%1,%2,%3}, [%4];"
        : "=r"(r[0]), "=r"(r[1]), "=r"(r[2]), "=r"(r[3]) : "r"(addr));
}
__device__ __forceinline__ void mma_fp16(float* c, const uint32_t* a,
                                         uint32_t b0, uint32_t b1) {
    asm volatile("mma.sync.aligned.m16n8k16.row.col.f32.f16.f16.f32 "
        "{%0,%1,%2,%3},{%4,%5,%6,%7},{%8,%9},{%0,%1,%2,%3};"
        : "+f"(c[0]), "+f"(c[1]), "+f"(c[2]), "+f"(c[3])
        : "r"(a[0]), "r"(a[1]), "r"(a[2]), "r"(a[3]), "r"(b0), "r"(b1));
}

// ---------------------------------------------------------------------------
// Kernel 1: fused X-quantize (HBM-bound) + Frobenius sums (latency-bound).
//   blocks [0, NCONV_BLOCKS):   convert X -> fp16
//   blocks [NCONV_BLOCKS,+40):  per-(tensor,task) sum of squares
// Independent tasks; sumsq latency hides under convert bandwidth.
// ---------------------------------------------------------------------------
__global__ __launch_bounds__(256)
void k_prep0(const float* __restrict__ x,
             const float* __restrict__ Aq, const float* __restrict__ Bq,
             const float* __restrict__ Av, const float* __restrict__ Bv) {
    if (blockIdx.x < NCONV_BLOCKS) {
        size_t i = ((size_t)blockIdx.x * 256 + threadIdx.x) * 4;
        float4 v = __ldg((const float4*)(x + i));
        __half h0 = __float2half(v.x), h1 = __float2half(v.y),
               h2 = __float2half(v.z), h3 = __float2half(v.w);
        uint2 hh = make_uint2(
            (uint32_t)__half_as_ushort(h0) | ((uint32_t)__half_as_ushort(h1) << 16),
            (uint32_t)__half_as_ushort(h2) | ((uint32_t)__half_as_ushort(h3) << 16));
        *(uint2*)(g_Xh + i) = hh;
        return;
    }
    int b = blockIdx.x - NCONV_BLOCKS;     // 0..39
    const float* base;
    switch (b / NUM_T) {
        case 0:  base = Aq; break;
        case 1:  base = Bq; break;
        case 2:  base = Av; break;
        default: base = Bv; break;
    }
    const float4* p = (const float4*)(base + (b % NUM_T) * SEG);
    float s = 0.f;
    for (int i = threadIdx.x; i < SEG / 4; i += 256) {
        float4 v = __ldg(p + i);
        s += v.x * v.x + v.y * v.y + v.z * v.z + v.w * v.w;
    }
    #pragma unroll
    for (int o = 16; o > 0; o >>= 1)
        s += __shfl_xor_sync(0xFFFFFFFF, s, o);
    __shared__ float red[8];
    if ((threadIdx.x & 31) == 0) red[threadIdx.x >> 5] = s;
    __syncthreads();
    if (threadIdx.x == 0) {
        float t = 0.f;
        #pragma unroll
        for (int i = 0; i < 8; i++) t += red[i];
        g_sumsq[b] = t;
    }
}

// ---------------------------------------------------------------------------
// Kernel 2: build W_eff -> fp16 (inline softmax gate weights per block).
// 8 e-rows x 256 d-cols per block.
// ---------------------------------------------------------------------------
__global__ __launch_bounds__(256)
void k_weff(const float* __restrict__ Aq, const float* __restrict__ Bq,
            const float* __restrict__ Av, const float* __restrict__ Bv,
            const float* __restrict__ qkvw,
            const float* __restrict__ logits, const float* __restrict__ alpha) {
    const int bid = blockIdx.x;
    const int d   = (bid % WEFF_DTILES) * 256 + threadIdx.x;
    const int e0  = (bid / WEFF_DTILES) * WEFF_EROWS;
    const int tx  = threadIdx.x;

    float acc[WEFF_EROWS];
    #pragma unroll
    for (int e = 0; e < WEFF_EROWS; e++) acc[e] = 0.f;

    bool is_q = (e0 < DIM_D);
    bool is_v = (e0 >= 2 * DIM_D);
    if (is_q || is_v) {
        __shared__ float sw[NUM_T];
        __shared__ __align__(16) float sB[NUM_T * RANK_R * WEFF_EROWS];  // [i][e]

        if (tx == 0) {
            float mx = -1e30f;
            float lg[NUM_T];
            #pragma unroll
            for (int t = 0; t < NUM_T; t++) { lg[t] = __ldg(logits + t); mx = fmaxf(mx, lg[t]); }
            float e[NUM_T], se = 0.f;
            #pragma unroll
            for (int t = 0; t < NUM_T; t++) { e[t] = expf(lg[t] - mx); se += e[t]; }
            #pragma unroll
            for (int t = 0; t < NUM_T; t++) {
                float coef = (e[t] / se) * __ldg(alpha + t);
                float nrm = is_q
                    ? sqrtf(g_sumsq[t])      * sqrtf(g_sumsq[10 + t])
                    : sqrtf(g_sumsq[20 + t]) * sqrtf(g_sumsq[30 + t]);
                sw[t] = coef / (nrm + 1e-8f);
            }
        }
        __syncthreads();

        const float* Am = is_q ? Aq : Av;
        const float* Bm = is_q ? Bq : Bv;
        int el0 = is_q ? e0 : (e0 - 2 * DIM_D);
        for (int idx = tx; idx < NUM_T * RANK_R * WEFF_EROWS; idx += 256) {
            int i = idx >> 3, e = idx & 7;
            int t = i >> 4,  r = i & 15;
            sB[idx] = sw[t] * Bm[((size_t)t * DIM_D + el0 + e) * RANK_R + r];
        }
        __syncthreads();

        const float4* sB4 = (const float4*)sB;
        #pragma unroll 32
        for (int i = 0; i < NUM_T * RANK_R; i++) {
            float a = __ldg(Am + (size_t)i * DIM_D + d);
            float4 b0 = sB4[i * 2 + 0];
            float4 b1 = sB4[i * 2 + 1];
            acc[0] += a * b0.x;  acc[1] += a * b0.y;
            acc[2] += a * b0.z;  acc[3] += a * b0.w;
            acc[4] += a * b1.x;  acc[5] += a * b1.y;
            acc[6] += a * b1.z;  acc[7] += a * b1.w;
        }
    }
    #pragma unroll
    for (int e = 0; e < WEFF_EROWS; e++) {
        float val = qkvw[(size_t)(e0 + e) * DIM_D + d] + acc[e];
        g_Wh[(size_t)(e0 + e) * DIM_D + d] = __half_as_ushort(__float2half(val));
    }
}

// ---------------------------------------------------------------------------
// Kernel 3: HMMA GEMM  out = Xh @ Wh^T + bias   (R5 config, verbatim)
// ---------------------------------------------------------------------------
__global__ __launch_bounds__(256, 2)
void k_gemm_mma(const float* __restrict__ bias, float* __restrict__ out) {
    extern __shared__ __align__(128) char smem[];
    const uint32_t sb = smem_u32(smem);
    const int tid = threadIdx.x;
    const int lid = tid & 31;
    const int wid = tid >> 5;
    const int wm = wid & 3;          // 4 warps in M, 32 rows each
    const int wn = wid >> 2;         // 2 warps in N, 64 cols each
    const int m0 = blockIdx.y * BM;
    const int n0 = blockIdx.x * BN;

    float acc[2][8][4];
    #pragma unroll
    for (int i = 0; i < 2; i++)
        #pragma unroll
        for (int j = 0; j < 8; j++)
            #pragma unroll
            for (int q = 0; q < 4; q++) acc[i][j][q] = 0.f;

    const uint32_t a_off = (uint32_t)(lid & 15) * ROWB + (uint32_t)(lid >> 4) * 16;
    const int b_nloc = (lid < 16) ? (lid & 7) : 8 + (lid & 7);
    const uint32_t b_off = (uint32_t)b_nloc * ROWB + (uint32_t)((lid >> 3) & 1) * 16;

    auto load_stage = [&](int s) {
        uint32_t buf = sb + (uint32_t)(s % NSTAGE) * STAGEB;
        int k0 = s * BK;
        #pragma unroll
        for (int i = 0; i < 4; i++) {
            int v = tid + i * 256;
            int arr = v >> 9;            // 0: Xh, 1: Wh
            int idx = v & 511;
            int r = idx >> 2, c = idx & 3;
            uint32_t dst = buf + (uint32_t)arr * ARRB + (uint32_t)r * ROWB + (uint32_t)c * 16;
            const unsigned short* src = arr == 0
                ? g_Xh + (size_t)(m0 + r) * DIM_D + k0 + c * 8
                : g_Wh + (size_t)(n0 + r) * DIM_D + k0 + c * 8;
            CP16(dst, src);
        }
    };

    load_stage(0); CP_COMMIT();
    load_stage(1); CP_COMMIT();
    load_stage(2); CP_COMMIT();

    for (int s = 0; s < KSTAGES; s++) {
        CP_WAIT2();
        __syncthreads();
        if (s + 3 < KSTAGES) load_stage(s + 3);
        CP_COMMIT();

        uint32_t buf = sb + (uint32_t)(s % NSTAGE) * STAGEB;
        #pragma unroll
        for (int kk = 0; kk < 2; kk++) {
            uint32_t koff = (uint32_t)kk * 32;
            uint32_t ra[2][4];
            #pragma unroll
            for (int mt = 0; mt < 2; mt++)
                ldsm_x4(ra[mt], buf + (uint32_t)(wm * 32 + mt * 16) * ROWB + koff + a_off);
            #pragma unroll
            for (int half = 0; half < 2; half++) {
                uint32_t rb[2][4];
                #pragma unroll
                for (int g = 0; g < 2; g++)
                    ldsm_x4(rb[g], buf + ARRB +
                        (uint32_t)(wn * 64 + (half * 2 + g) * 16) * ROWB + koff + b_off);
                #pragma unroll
                for (int mt = 0; mt < 2; mt++)
                    #pragma unroll
                    for (int n4 = 0; n4 < 4; n4++) {
                        uint32_t b0 = rb[n4 >> 1][(n4 & 1) * 2];
                        uint32_t b1 = rb[n4 >> 1][(n4 & 1) * 2 + 1];
                        mma_fp16(acc[mt][half * 4 + n4], ra[mt], b0, b1);
                    }
            }
        }
    }

    const int r0 = m0 + wm * 32 + (lid >> 2);
    const int cb = n0 + wn * 64 + (lid & 3) * 2;
    #pragma unroll
    for (int nt = 0; nt < 8; nt++) {
        float2 bv = *(const float2*)(bias + cb + nt * 8);
        #pragma unroll
        for (int mt = 0; mt < 2; mt++) {
            int r = r0 + mt * 16;
            float2 v0 = make_float2(acc[mt][nt][0] + bv.x, acc[mt][nt][1] + bv.y);
            float2 v1 = make_float2(acc[mt][nt][2] + bv.x, acc[mt][nt][3] + bv.y);
            *(float2*)(out + (size_t)r * DIM_N + cb + nt * 8) = v0;
            *(float2*)(out + (size_t)(r + 8) * DIM_N + cb + nt * 8) = v1;
        }
    }
}

// ---------------------------------------------------------------------------
// Launch
// ---------------------------------------------------------------------------
extern "C" void kernel_launch(void* const* d_in, const int* in_sizes, int n_in,
                              void* d_out, int out_size) {
    const float* x      = (const float*)d_in[0];
    const float* Aq     = (const float*)d_in[1];
    const float* Bq     = (const float*)d_in[2];
    const float* Av     = (const float*)d_in[3];
    const float* Bv     = (const float*)d_in[4];
    const float* qkvw   = (const float*)d_in[5];
    const float* qkvb   = (const float*)d_in[6];
    const float* logits = (const float*)d_in[7];
    const float* alpha  = (const float*)d_in[8];
    float* out = (float*)d_out;

    cudaFuncSetAttribute(k_gemm_mma, cudaFuncAttributeMaxDynamicSharedMemorySize, SMEM_TOTAL);

    k_prep0   <<<NCONV_BLOCKS + NSUMSQ_BLOCKS, 256>>>(x, Aq, Bq, Av, Bv);
    k_weff    <<<WEFF_DTILES * WEFF_ETILES, 256>>>(Aq, Bq, Av, Bv, qkvw, logits, alpha);
    k_gemm_mma<<<dim3(DIM_N / BN, BATCH_M / BM), 256, SMEM_TOTAL>>>(qkvb, out);
}

// round 11
// speedup vs baseline: 1.1347x; 1.0095x over previous
#include <cuda_runtime.h>
#include <cuda_fp16.h>
#include <math.h>
#include <stdint.h>

// Problem constants
#define BATCH_M   16384   // B*S
#define DIM_D     768
#define DIM_N     2304    // 3*D
#define NUM_T     10
#define RANK_R    16
#define SEG       (RANK_R * DIM_D)

// GEMM tiling (R5 config — proven fastest): CTA 128x128, 8 warps, BK=32
#define BM 128
#define BN 128
#define BK 32
#define KSTAGES (DIM_D / BK)       // 24

#define ROWB     80
#define ARRB     10240             // 128 rows * 80B
#define STAGEB   20480
#define NSTAGE   4
#define SMEM_TOTAL (NSTAGE * STAGEB)

// prep0 grid split: convert blocks (8 floats/thread) then sumsq blocks
#define NCONV_BLOCKS 6144          // 6144 blocks * 256 thr * 8 elems = X
#define NSUMSQ_BLOCKS 40

// weff tiling
#define WEFF_DTILES  3             // 768 / 256
#define WEFF_EROWS   8
#define WEFF_ETILES  (DIM_N / WEFF_EROWS)   // 288

// Device scratch (no cudaMalloc allowed)
__device__ float g_sumsq[40];
__device__ __align__(16) unsigned short g_Xh[(size_t)BATCH_M * DIM_D];
__device__ __align__(16) unsigned short g_Wh[(size_t)DIM_N * DIM_D];

// ---------------------------------------------------------------------------
// Helpers
// ---------------------------------------------------------------------------
__device__ __forceinline__ uint32_t smem_u32(const void* p) {
    uint32_t a;
    asm("{ .reg .u64 t; cvta.to.shared.u64 t, %1; cvt.u32.u64 %0, t; }" : "=r"(a) : "l"(p));
    return a;
}
#define CP16(dst, src) \
    asm volatile("cp.async.cg.shared.global [%0], [%1], 16;" :: "r"(dst), "l"(src))
#define CP_COMMIT() asm volatile("cp.async.commit_group;" ::: "memory")
#define CP_WAIT2()  asm volatile("cp.async.wait_group 2;"  ::: "memory")

__device__ __forceinline__ void ldsm_x4(uint32_t* r, uint32_t addr) {
    asm volatile("ldmatrix.sync.aligned.m8n8.x4.shared.b16 {%0,%1,%2,%3}, [%4];"
        : "=r"(r[0]), "=r"(r[1]), "=r"(r[2]), "=r"(r[3]) : "r"(addr));
}
__device__ __forceinline__ void mma_fp16(float* c, const uint32_t* a,
                                         uint32_t b0, uint32_t b1) {
    asm volatile("mma.sync.aligned.m16n8k16.row.col.f32.f16.f16.f32 "
        "{%0,%1,%2,%3},{%4,%5,%6,%7},{%8,%9},{%0,%1,%2,%3};"
        : "+f"(c[0]), "+f"(c[1]), "+f"(c[2]), "+f"(c[3])
        : "r"(a[0]), "r"(a[1]), "r"(a[2]), "r"(a[3]), "r"(b0), "r"(b1));
}

// ---------------------------------------------------------------------------
// Kernel 1: fused X-quantize (HBM-bound, 8 elems/thread, MLP=2 LDG.128)
//           + Frobenius sums (latency-bound, hides under convert).
//   blocks [0, NCONV_BLOCKS):   convert X -> fp16
//   blocks [NCONV_BLOCKS,+40):  per-(tensor,task) sum of squares
// ---------------------------------------------------------------------------
__global__ __launch_bounds__(256)
void k_prep0(const float* __restrict__ x,
             const float* __restrict__ Aq, const float* __restrict__ Bq,
             const float* __restrict__ Av, const float* __restrict__ Bv) {
    if (blockIdx.x < NCONV_BLOCKS) {
        size_t i = ((size_t)blockIdx.x * 256 + threadIdx.x) * 8;
        float4 v0 = __ldg((const float4*)(x + i));
        float4 v1 = __ldg((const float4*)(x + i + 4));
        uint4 hh;
        hh.x = (uint32_t)__half_as_ushort(__float2half(v0.x))
             | ((uint32_t)__half_as_ushort(__float2half(v0.y)) << 16);
        hh.y = (uint32_t)__half_as_ushort(__float2half(v0.z))
             | ((uint32_t)__half_as_ushort(__float2half(v0.w)) << 16);
        hh.z = (uint32_t)__half_as_ushort(__float2half(v1.x))
             | ((uint32_t)__half_as_ushort(__float2half(v1.y)) << 16);
        hh.w = (uint32_t)__half_as_ushort(__float2half(v1.z))
             | ((uint32_t)__half_as_ushort(__float2half(v1.w)) << 16);
        *(uint4*)(g_Xh + i) = hh;
        return;
    }
    int b = blockIdx.x - NCONV_BLOCKS;     // 0..39
    const float* base;
    switch (b / NUM_T) {
        case 0:  base = Aq; break;
        case 1:  base = Bq; break;
        case 2:  base = Av; break;
        default: base = Bv; break;
    }
    const float4* p = (const float4*)(base + (b % NUM_T) * SEG);
    float s = 0.f;
    for (int i = threadIdx.x; i < SEG / 4; i += 256) {
        float4 v = __ldg(p + i);
        s += v.x * v.x + v.y * v.y + v.z * v.z + v.w * v.w;
    }
    #pragma unroll
    for (int o = 16; o > 0; o >>= 1)
        s += __shfl_xor_sync(0xFFFFFFFF, s, o);
    __shared__ float red[8];
    if ((threadIdx.x & 31) == 0) red[threadIdx.x >> 5] = s;
    __syncthreads();
    if (threadIdx.x == 0) {
        float t = 0.f;
        #pragma unroll
        for (int i = 0; i < 8; i++) t += red[i];
        g_sumsq[b] = t;
    }
}

// ---------------------------------------------------------------------------
// Kernel 2: build W_eff -> fp16 (inline softmax gate weights per block).
// 8 e-rows x 256 d-cols per block.
// ---------------------------------------------------------------------------
__global__ __launch_bounds__(256)
void k_weff(const float* __restrict__ Aq, const float* __restrict__ Bq,
            const float* __restrict__ Av, const float* __restrict__ Bv,
            const float* __restrict__ qkvw,
            const float* __restrict__ logits, const float* __restrict__ alpha) {
    const int bid = blockIdx.x;
    const int d   = (bid % WEFF_DTILES) * 256 + threadIdx.x;
    const int e0  = (bid / WEFF_DTILES) * WEFF_EROWS;
    const int tx  = threadIdx.x;

    float acc[WEFF_EROWS];
    #pragma unroll
    for (int e = 0; e < WEFF_EROWS; e++) acc[e] = 0.f;

    bool is_q = (e0 < DIM_D);
    bool is_v = (e0 >= 2 * DIM_D);
    if (is_q || is_v) {
        __shared__ float sw[NUM_T];
        __shared__ __align__(16) float sB[NUM_T * RANK_R * WEFF_EROWS];  // [i][e]

        if (tx == 0) {
            float mx = -1e30f;
            float lg[NUM_T];
            #pragma unroll
            for (int t = 0; t < NUM_T; t++) { lg[t] = __ldg(logits + t); mx = fmaxf(mx, lg[t]); }
            float e[NUM_T], se = 0.f;
            #pragma unroll
            for (int t = 0; t < NUM_T; t++) { e[t] = expf(lg[t] - mx); se += e[t]; }
            #pragma unroll
            for (int t = 0; t < NUM_T; t++) {
                float coef = (e[t] / se) * __ldg(alpha + t);
                float nrm = is_q
                    ? sqrtf(g_sumsq[t])      * sqrtf(g_sumsq[10 + t])
                    : sqrtf(g_sumsq[20 + t]) * sqrtf(g_sumsq[30 + t]);
                sw[t] = coef / (nrm + 1e-8f);
            }
        }
        __syncthreads();

        const float* Am = is_q ? Aq : Av;
        const float* Bm = is_q ? Bq : Bv;
        int el0 = is_q ? e0 : (e0 - 2 * DIM_D);
        for (int idx = tx; idx < NUM_T * RANK_R * WEFF_EROWS; idx += 256) {
            int i = idx >> 3, e = idx & 7;
            int t = i >> 4,  r = i & 15;
            sB[idx] = sw[t] * Bm[((size_t)t * DIM_D + el0 + e) * RANK_R + r];
        }
        __syncthreads();

        const float4* sB4 = (const float4*)sB;
        #pragma unroll 32
        for (int i = 0; i < NUM_T * RANK_R; i++) {
            float a = __ldg(Am + (size_t)i * DIM_D + d);
            float4 b0 = sB4[i * 2 + 0];
            float4 b1 = sB4[i * 2 + 1];
            acc[0] += a * b0.x;  acc[1] += a * b0.y;
            acc[2] += a * b0.z;  acc[3] += a * b0.w;
            acc[4] += a * b1.x;  acc[5] += a * b1.y;
            acc[6] += a * b1.z;  acc[7] += a * b1.w;
        }
    }
    #pragma unroll
    for (int e = 0; e < WEFF_EROWS; e++) {
        float val = qkvw[(size_t)(e0 + e) * DIM_D + d] + acc[e];
        g_Wh[(size_t)(e0 + e) * DIM_D + d] = __half_as_ushort(__float2half(val));
    }
}

// ---------------------------------------------------------------------------
// Kernel 3: HMMA GEMM  out = Xh @ Wh^T + bias   (R5 config, verbatim)
// ---------------------------------------------------------------------------
__global__ __launch_bounds__(256, 2)
void k_gemm_mma(const float* __restrict__ bias, float* __restrict__ out) {
    extern __shared__ __align__(128) char smem[];
    const uint32_t sb = smem_u32(smem);
    const int tid = threadIdx.x;
    const int lid = tid & 31;
    const int wid = tid >> 5;
    const int wm = wid & 3;          // 4 warps in M, 32 rows each
    const int wn = wid >> 2;         // 2 warps in N, 64 cols each
    const int m0 = blockIdx.y * BM;
    const int n0 = blockIdx.x * BN;

    float acc[2][8][4];
    #pragma unroll
    for (int i = 0; i < 2; i++)
        #pragma unroll
        for (int j = 0; j < 8; j++)
            #pragma unroll
            for (int q = 0; q < 4; q++) acc[i][j][q] = 0.f;

    const uint32_t a_off = (uint32_t)(lid & 15) * ROWB + (uint32_t)(lid >> 4) * 16;
    const int b_nloc = (lid < 16) ? (lid & 7) : 8 + (lid & 7);
    const uint32_t b_off = (uint32_t)b_nloc * ROWB + (uint32_t)((lid >> 3) & 1) * 16;

    auto load_stage = [&](int s) {
        uint32_t buf = sb + (uint32_t)(s % NSTAGE) * STAGEB;
        int k0 = s * BK;
        #pragma unroll
        for (int i = 0; i < 4; i++) {
            int v = tid + i * 256;
            int arr = v >> 9;            // 0: Xh, 1: Wh
            int idx = v & 511;
            int r = idx >> 2, c = idx & 3;
            uint32_t dst = buf + (uint32_t)arr * ARRB + (uint32_t)r * ROWB + (uint32_t)c * 16;
            const unsigned short* src = arr == 0
                ? g_Xh + (size_t)(m0 + r) * DIM_D + k0 + c * 8
                : g_Wh + (size_t)(n0 + r) * DIM_D + k0 + c * 8;
            CP16(dst, src);
        }
    };

    load_stage(0); CP_COMMIT();
    load_stage(1); CP_COMMIT();
    load_stage(2); CP_COMMIT();

    for (int s = 0; s < KSTAGES; s++) {
        CP_WAIT2();
        __syncthreads();
        if (s + 3 < KSTAGES) load_stage(s + 3);
        CP_COMMIT();

        uint32_t buf = sb + (uint32_t)(s % NSTAGE) * STAGEB;
        #pragma unroll
        for (int kk = 0; kk < 2; kk++) {
            uint32_t koff = (uint32_t)kk * 32;
            uint32_t ra[2][4];
            #pragma unroll
            for (int mt = 0; mt < 2; mt++)
                ldsm_x4(ra[mt], buf + (uint32_t)(wm * 32 + mt * 16) * ROWB + koff + a_off);
            #pragma unroll
            for (int half = 0; half < 2; half++) {
                uint32_t rb[2][4];
                #pragma unroll
                for (int g = 0; g < 2; g++)
                    ldsm_x4(rb[g], buf + ARRB +
                        (uint32_t)(wn * 64 + (half * 2 + g) * 16) * ROWB + koff + b_off);
                #pragma unroll
                for (int mt = 0; mt < 2; mt++)
                    #pragma unroll
                    for (int n4 = 0; n4 < 4; n4++) {
                        uint32_t b0 = rb[n4 >> 1][(n4 & 1) * 2];
                        uint32_t b1 = rb[n4 >> 1][(n4 & 1) * 2 + 1];
                        mma_fp16(acc[mt][half * 4 + n4], ra[mt], b0, b1);
                    }
            }
        }
    }

    const int r0 = m0 + wm * 32 + (lid >> 2);
    const int cb = n0 + wn * 64 + (lid & 3) * 2;
    #pragma unroll
    for (int nt = 0; nt < 8; nt++) {
        float2 bv = *(const float2*)(bias + cb + nt * 8);
        #pragma unroll
        for (int mt = 0; mt < 2; mt++) {
            int r = r0 + mt * 16;
            float2 v0 = make_float2(acc[mt][nt][0] + bv.x, acc[mt][nt][1] + bv.y);
            float2 v1 = make_float2(acc[mt][nt][2] + bv.x, acc[mt][nt][3] + bv.y);
            *(float2*)(out + (size_t)r * DIM_N + cb + nt * 8) = v0;
            *(float2*)(out + (size_t)(r + 8) * DIM_N + cb + nt * 8) = v1;
        }
    }
}

// ---------------------------------------------------------------------------
// Launch
// ---------------------------------------------------------------------------
extern "C" void kernel_launch(void* const* d_in, const int* in_sizes, int n_in,
                              void* d_out, int out_size) {
    const float* x      = (const float*)d_in[0];
    const float* Aq     = (const float*)d_in[1];
    const float* Bq     = (const float*)d_in[2];
    const float* Av     = (const float*)d_in[3];
    const float* Bv     = (const float*)d_in[4];
    const float* qkvw   = (const float*)d_in[5];
    const float* qkvb   = (const float*)d_in[6];
    const float* logits = (const float*)d_in[7];
    const float* alpha  = (const float*)d_in[8];
    float* out = (float*)d_out;

    cudaFuncSetAttribute(k_gemm_mma, cudaFuncAttributeMaxDynamicSharedMemorySize, SMEM_TOTAL);

    k_prep0   <<<NCONV_BLOCKS + NSUMSQ_BLOCKS, 256>>>(x, Aq, Bq, Av, Bv);
    k_weff    <<<WEFF_DTILES * WEFF_ETILES, 256>>>(Aq, Bq, Av, Bv, qkvw, logits, alpha);
    k_gemm_mma<<<dim3(DIM_N / BN, BATCH_M / BM), 256, SMEM_TOTAL>>>(qkvb, out);
}